// round 5
// baseline (speedup 1.0000x reference)
#include <cuda_runtime.h>

// Problem constants (fixed by the reference)
#define NG 128      // num_graphs
#define NT 32       // num thetas
#define NS 32       // bump steps
#define NF 128      // num features
#define NSPLIT 8    // blocks per graph
#define SCALE_F 100.0f
#define R_F 1.1f

// Scratch (device globals: no allocation allowed). Layout [g][s][t].
__device__ float g_E[NG * NS * NT];
__device__ float g_C[NG * NS * NT];

__global__ void zero_kernel() {
    int n = NG * NS * NT;
    for (int i = blockIdx.x * blockDim.x + threadIdx.x; i < n;
         i += gridDim.x * blockDim.x) {
        g_E[i] = 0.0f;
        g_C[i] = 0.0f;
    }
}

// batch may be int32 (JAX default, x64 disabled) or int64 (reference dtype).
// n_nodes is the LOGICAL element count (derived from x, so it is trustworthy).
// If int64: word at index 2*(n-1)+1 is the high half of the last element; all
// graph ids are < 128 so it is 0. If int32: word at index n-1 is the last
// (largest, sorted) graph id != 0. Both reads are in-bounds for both dtypes
// only if we probe the int32 word at (n-1) — which is the high half of element
// (n-1)/2 for int64 (still 0) and the last id for int32.
__device__ __forceinline__ bool batch_is_i64(const int* b32, int n_nodes) {
    return b32[n_nodes - 1] == 0;
}

__device__ int lower_bound_batch(const int* b32, int n, int key, bool is64) {
    const long long* b64 = (const long long*)b32;
    int lo = 0, hi = n;
    while (lo < hi) {
        int m = (lo + hi) >> 1;
        long long val = is64 ? b64[m] : (long long)b32[m];
        if (val < (long long)key) lo = m + 1; else hi = m;
    }
    return lo;
}

__global__ __launch_bounds__(256)
void ect_main_kernel(const float* __restrict__ x,
                     const int* __restrict__ batch,
                     int n_nodes,
                     const float* __restrict__ v) {
    __shared__ float vT[NF][NT];        // 16 KB, vT[k][t]
    __shared__ float xs[32][132];       // 16.9 KB, pad 4 -> conflict-free LDS.128
    __shared__ float accE[NT][NS + 1];  // 4.2 KB (pad avoids t-major bank clash)
    __shared__ float accC[NT][NS + 1];  // 4.2 KB
    __shared__ int s_range[2];

    const int tid  = threadIdx.x;
    const int lane = tid & 31;   // node within chunk
    const int w    = tid >> 5;   // warp id 0..7
    const int tb   = w * 4;      // this warp covers thetas tb..tb+3

    const bool is64 = batch_is_i64(batch, n_nodes);
    const int g = blockIdx.x;

    // Load v transposed: v is [NT][NF] row-major -> vT[k][t]
    for (int i = tid; i < NF * NT; i += 256) {
        int t = i >> 7;     // /NF
        int k = i & (NF - 1);
        vT[k][t] = v[i];
    }
    // Zero accumulators
    for (int i = tid; i < NT * (NS + 1); i += 256) {
        (&accE[0][0])[i] = 0.0f;
        (&accC[0][0])[i] = 0.0f;
    }
    if (tid == 0) {
        s_range[0] = lower_bound_batch(batch, n_nodes, g, is64);
        s_range[1] = lower_bound_batch(batch, n_nodes, g + 1, is64);
    }
    __syncthreads();

    const int glo = s_range[0];
    const int len = s_range[1] - glo;
    const int jsl = blockIdx.y;
    const int start = glo + (int)(((long long)len * jsl) / NSPLIT);
    const int end   = glo + (int)(((long long)len * (jsl + 1)) / NSPLIT);

    const float step     = (2.0f * R_F) / 31.0f;   // matches fp32 linspace step
    const float inv_step = 1.0f / step;
    const float Wd       = 0.16f * inv_step;       // |z|<=16 window in grid units
    const float lin0     = -R_F;

    for (int base = start; base < end; base += 32) {
        __syncthreads();  // previous chunk's xs reads done
        // Load 32 node rows (float4, coalesced) into padded smem
        for (int i4 = tid; i4 < 32 * 32; i4 += 256) {
            int n  = i4 >> 5;
            int k4 = i4 & 31;
            int node = base + n;
            float4 val = make_float4(0.f, 0.f, 0.f, 0.f);
            if (node < end) val = ((const float4*)x)[(long long)node * 32 + k4];
            *(float4*)&xs[n][k4 * 4] = val;
        }
        __syncthreads();

        // nh for (node=lane, thetas tb..tb+3): 16 FFMA : 5 LDS.128 per 4-k step
        float a0 = 0.f, a1 = 0.f, a2 = 0.f, a3 = 0.f;
        #pragma unroll 4
        for (int k = 0; k < NF; k += 4) {
            float4 xk = *(const float4*)&xs[lane][k];
            float4 vv;
            vv = *(const float4*)&vT[k + 0][tb];
            a0 += xk.x * vv.x; a1 += xk.x * vv.y; a2 += xk.x * vv.z; a3 += xk.x * vv.w;
            vv = *(const float4*)&vT[k + 1][tb];
            a0 += xk.y * vv.x; a1 += xk.y * vv.y; a2 += xk.y * vv.z; a3 += xk.y * vv.w;
            vv = *(const float4*)&vT[k + 2][tb];
            a0 += xk.z * vv.x; a1 += xk.z * vv.y; a2 += xk.z * vv.z; a3 += xk.z * vv.w;
            vv = *(const float4*)&vT[k + 3][tb];
            a0 += xk.w * vv.x; a1 += xk.w * vv.y; a2 += xk.w * vv.z; a3 += xk.w * vv.w;
        }

        // Windowed sigmoid accumulation (near-step exploit):
        //   s <  s_lo : sigmoid ~ 0, skip
        //   s >= s_hi : sigmoid ~ 1, encoded as unit delta at s_hi (prefix-sum
        //               over s in the epilogue reconstructs the ones-tail)
        if (base + lane < end) {
            float hv[4] = {a0, a1, a2, a3};
            #pragma unroll
            for (int jj = 0; jj < 4; jj++) {
                float h = hv[jj];
                float a = (h + R_F) * inv_step;     // grid-unit position
                int s_lo = (int)ceilf(a - Wd);
                int s_hi = (int)ceilf(a + Wd);
                s_lo = max(0, min(s_lo, 32));
                s_hi = max(0, min(s_hi, 32));
                int t = tb + jj;
                for (int s = s_lo; s < s_hi; s++) {
                    float z = SCALE_F * ((lin0 + s * step) - h);
                    float f = 1.0f / (1.0f + __expf(-z));
                    atomicAdd(&accE[t][s], f);
                }
                if (s_hi < 32) atomicAdd(&accC[t][s_hi], 1.0f);
            }
        }
    }
    __syncthreads();

    // Flush shared accumulators to global scratch [g][s][t]
    for (int i = tid; i < NS * NT; i += 256) {
        int s = i >> 5;
        int t = i & 31;
        float e = accE[t][s];
        float c = accC[t][s];
        if (e != 0.0f) atomicAdd(&g_E[(g * NS + s) * NT + t], e);
        if (c != 0.0f) atomicAdd(&g_C[(g * NS + s) * NT + t], c);
    }
}

// Epilogue: prefix-sum C over s (reconstruct sigmoid~1 tails), add E, subtract
// count_g * sigmoid(100*(lin_s - R)) (the exact constant pad term).
__global__ void ect_epilogue_kernel(const int* __restrict__ batch, int n_nodes,
                                    float* __restrict__ out) {
    int g = blockIdx.x;
    int t = threadIdx.x;  // 32 threads
    bool is64 = batch_is_i64(batch, n_nodes);
    __shared__ int cnt_s;
    if (t == 0) {
        int lo = lower_bound_batch(batch, n_nodes, g, is64);
        int hi = lower_bound_batch(batch, n_nodes, g + 1, is64);
        cnt_s = hi - lo;
    }
    __syncthreads();
    float cnt = (float)cnt_s;
    const float step = (2.0f * R_F) / 31.0f;
    float p = 0.0f;
    for (int s = 0; s < NS; s++) {
        int idx = (g * NS + s) * NT + t;
        p += g_C[idx];
        float z0 = SCALE_F * ((-R_F + s * step) - R_F);
        float s0 = 1.0f / (1.0f + expf(-z0));   // exact constant pad term
        out[idx] = g_E[idx] + p - cnt * s0;
    }
}

extern "C" void kernel_launch(void* const* d_in, const int* in_sizes, int n_in,
                              void* d_out, int out_size) {
    const float* x     = (const float*)d_in[0];
    const int*   batch = (const int*)d_in[1];   // int32 or int64, sniffed on device
    const float* v     = (const float*)d_in[3];
    // Derive node count from x ([N, 128] float32) — immune to how the harness
    // counts int64 elements for the batch array.
    int n_nodes = in_sizes[0] / NF;

    zero_kernel<<<256, 256>>>();
    dim3 grid(NG, NSPLIT);
    ect_main_kernel<<<grid, 256>>>(x, batch, n_nodes, v);
    ect_epilogue_kernel<<<NG, 32>>>(batch, n_nodes, (float*)d_out);
}

// round 6
// speedup vs baseline: 1.6396x; 1.6396x over previous
#include <cuda_runtime.h>

// Problem constants (fixed by the reference)
#define NG 128      // num_graphs
#define NT 32       // num thetas
#define NS 32       // bump steps
#define NF 128      // num features
#define NSPLIT 16   // blocks per graph
#define SCALE_F 100.0f
#define R_F 1.1f

// Scratch (device global: no allocation allowed). Layout [g][t][s]:
// sum over nodes of tanh(0.5*SCALE*(lin_s - h_{n,t})).
__device__ float g_T[NG * NT * NS];

__global__ void zero_kernel() {
    int n = NG * NT * NS;
    for (int i = blockIdx.x * blockDim.x + threadIdx.x; i < n;
         i += gridDim.x * blockDim.x)
        g_T[i] = 0.0f;
}

// batch may be int32 (JAX default) or int64 (reference dtype). n_nodes is the
// LOGICAL element count (derived from x). Probe the int32 word at n-1: for
// int64 it is the high half of element (n-1)/2 (== 0, ids < 128); for int32
// it is the last (largest, sorted) graph id != 0. In-bounds either way.
__device__ __forceinline__ bool batch_is_i64(const int* b32, int n_nodes) {
    return b32[n_nodes - 1] == 0;
}

__device__ int lower_bound_batch(const int* b32, int n, int key, bool is64) {
    const long long* b64 = (const long long*)b32;
    int lo = 0, hi = n;
    while (lo < hi) {
        int m = (lo + hi) >> 1;
        long long val = is64 ? b64[m] : (long long)b32[m];
        if (val < (long long)key) lo = m + 1; else hi = m;
    }
    return lo;
}

__device__ __forceinline__ float tanh_ap(float xv) {
    float y;
    asm("tanh.approx.f32 %0, %1;" : "=f"(y) : "f"(xv));
    return y;
}

// Packed dual-FMA: d.lo += a.lo*b.lo; d.hi += a.hi*b.hi  (one FFMA2 issue)
__device__ __forceinline__ void ffma2(unsigned long long& d,
                                      unsigned long long a,
                                      unsigned long long b) {
    asm("fma.rn.f32x2 %0, %1, %2, %0;" : "+l"(d) : "l"(a), "l"(b));
}

__global__ __launch_bounds__(256)
void ect_main_kernel(const float* __restrict__ x,
                     const int* __restrict__ batch,
                     int n_nodes,
                     const float* __restrict__ v) {
    __shared__ float vP[NF / 2][NT][2];  // 16 KB: k-pair-packed v, [k2][t][{k,k+1}]
    __shared__ float xs[32][132];        // 16.9 KB, pad 4 -> conflict-free LDS.128
    __shared__ int s_range[2];

    const int tid  = threadIdx.x;
    const int lane = tid & 31;   // doubles as: node-in-chunk (matmul) and s (window)
    const int w    = tid >> 5;   // warp id 0..7
    const int tb   = w * 4;      // this warp covers thetas tb..tb+3
    const int g    = blockIdx.x;

    const bool is64 = batch_is_i64(batch, n_nodes);

    // Pack v: v is [NT][NF] row-major -> vP[k>>1][t][k&1]
    for (int i = tid; i < NF * NT; i += 256) {
        int t = i >> 7;          // / NF
        int k = i & (NF - 1);
        vP[k >> 1][t][k & 1] = v[i];
    }
    if (tid == 0)  s_range[0] = lower_bound_batch(batch, n_nodes, g, is64);
    if (tid == 32) s_range[1] = lower_bound_batch(batch, n_nodes, g + 1, is64);
    __syncthreads();

    const int glo = s_range[0];
    const int len = s_range[1] - glo;
    const int start = glo + (int)(((long long)len * blockIdx.y) / NSPLIT);
    const int end   = glo + (int)(((long long)len * (blockIdx.y + 1)) / NSPLIT);

    const float step = (2.0f * R_F) / (NS - 1);
    // per-lane constant: 0.5*SCALE*lin_s with s = lane
    const float Cs = 0.5f * SCALE_F * (-R_F + lane * step);

    // Register accumulators: acc[jj] holds Sum_n tanh(Cs - 0.5*SCALE*h_{n,tb+jj})
    float acc0 = 0.f, acc1 = 0.f, acc2 = 0.f, acc3 = 0.f;

    for (int base = start; base < end; base += 32) {
        __syncthreads();  // previous chunk's xs reads done
        // Load 32 node rows (float4, coalesced) into padded smem; pad with 0
        for (int i4 = tid; i4 < 32 * 32; i4 += 256) {
            int n  = i4 >> 5;
            int k4 = i4 & 31;
            int node = base + n;
            float4 val = make_float4(0.f, 0.f, 0.f, 0.f);
            if (node < end) val = ((const float4*)x)[(long long)node * 32 + k4];
            *(float4*)&xs[n][k4 * 4] = val;
        }
        __syncthreads();

        // Matmul: h for (node=lane, thetas tb..tb+3) via packed f32x2 FMA.
        // Per 4-k step: 8 FFMA2 + 1 LDS.128 (xs) + 4 LDS.128 (vP broadcast).
        unsigned long long p0 = 0, p1 = 0, p2 = 0, p3 = 0;
        #pragma unroll 4
        for (int k4 = 0; k4 < 32; ++k4) {
            ulonglong2 xk = *(const ulonglong2*)&xs[lane][k4 * 4];
            ulonglong2 va = *(const ulonglong2*)&vP[2 * k4][tb][0];      // t=tb,tb+1
            ulonglong2 vb = *(const ulonglong2*)&vP[2 * k4][tb + 2][0];  // t=tb+2,tb+3
            ffma2(p0, xk.x, va.x); ffma2(p1, xk.x, va.y);
            ffma2(p2, xk.x, vb.x); ffma2(p3, xk.x, vb.y);
            ulonglong2 vc = *(const ulonglong2*)&vP[2 * k4 + 1][tb][0];
            ulonglong2 vd = *(const ulonglong2*)&vP[2 * k4 + 1][tb + 2][0];
            ffma2(p0, xk.y, vc.x); ffma2(p1, xk.y, vc.y);
            ffma2(p2, xk.y, vd.x); ffma2(p3, xk.y, vd.y);
        }
        float2 f0 = *(float2*)&p0, f1 = *(float2*)&p1;
        float2 f2 = *(float2*)&p2, f3 = *(float2*)&p3;
        // hh = 0.5*SCALE*h, pre-scaled so the inner loop is one FADD + TANH + FADD
        float hh0 = 0.5f * SCALE_F * (f0.x + f0.y);
        float hh1 = 0.5f * SCALE_F * (f1.x + f1.y);
        float hh2 = 0.5f * SCALE_F * (f2.x + f2.y);
        float hh3 = 0.5f * SCALE_F * (f3.x + f3.y);

        // Warp transpose: broadcast each node's hh; lane = s accumulates its
        // tanh term in registers. sigma = 0.5 + 0.5*tanh(Cs - hh); the 0.5
        // constants are reconstructed from node counts in the epilogue.
        // Branchless, atomic-free, divergence-free.
        const int nv = min(32, end - base);
        #define ECT_BODY(r)                                              \
            {                                                            \
                float b0 = __shfl_sync(0xffffffffu, hh0, (r));           \
                float b1 = __shfl_sync(0xffffffffu, hh1, (r));           \
                float b2 = __shfl_sync(0xffffffffu, hh2, (r));           \
                float b3 = __shfl_sync(0xffffffffu, hh3, (r));           \
                acc0 += tanh_ap(Cs - b0);                                \
                acc1 += tanh_ap(Cs - b1);                                \
                acc2 += tanh_ap(Cs - b2);                                \
                acc3 += tanh_ap(Cs - b3);                                \
            }
        if (nv == 32) {
            #pragma unroll 8
            for (int r = 0; r < 32; ++r) ECT_BODY(r)
        } else {
            for (int r = 0; r < nv; ++r) ECT_BODY(r)
        }
        #undef ECT_BODY
    }

    // Single flush per warp: coalesced global float atomics (REDG), [g][t][s]
    atomicAdd(&g_T[(g * NT + tb + 0) * NS + lane], acc0);
    atomicAdd(&g_T[(g * NT + tb + 1) * NS + lane], acc1);
    atomicAdd(&g_T[(g * NT + tb + 2) * NS + lane], acc2);
    atomicAdd(&g_T[(g * NT + tb + 3) * NS + lane], acc3);
}

// Epilogue: sigma-sum = 0.5*cnt + 0.5*T; subtract cnt * sigmoid(100*(lin_s - R))
// (the exact constant pad term). Output layout [g][s][t].
__global__ void ect_epilogue_kernel(const int* __restrict__ batch, int n_nodes,
                                    float* __restrict__ out) {
    int g = blockIdx.x;
    int t = threadIdx.x;  // 32 threads
    bool is64 = batch_is_i64(batch, n_nodes);
    __shared__ int cnt_s;
    if (t == 0) {
        int lo = lower_bound_batch(batch, n_nodes, g, is64);
        int hi = lower_bound_batch(batch, n_nodes, g + 1, is64);
        cnt_s = hi - lo;
    }
    __syncthreads();
    float cnt = (float)cnt_s;
    const float step = (2.0f * R_F) / (NS - 1);
    for (int s = 0; s < NS; s++) {
        float T = g_T[(g * NT + t) * NS + s];
        float z0 = SCALE_F * ((-R_F + s * step) - R_F);
        float s0 = 1.0f / (1.0f + expf(-z0));   // exact constant pad term
        out[(g * NS + s) * NT + t] = 0.5f * cnt + 0.5f * T - cnt * s0;
    }
}

extern "C" void kernel_launch(void* const* d_in, const int* in_sizes, int n_in,
                              void* d_out, int out_size) {
    const float* x     = (const float*)d_in[0];
    const int*   batch = (const int*)d_in[1];   // int32 or int64, sniffed on device
    const float* v     = (const float*)d_in[3];
    // Derive node count from x ([N, 128] float32) — immune to how the harness
    // counts int64 elements for the batch array.
    int n_nodes = in_sizes[0] / NF;

    zero_kernel<<<256, 256>>>();
    dim3 grid(NG, NSPLIT);
    ect_main_kernel<<<grid, 256>>>(x, batch, n_nodes, v);
    ect_epilogue_kernel<<<NG, 32>>>(batch, n_nodes, (float*)d_out);
}

// round 7
// speedup vs baseline: 1.6448x; 1.0032x over previous
#include <cuda_runtime.h>

// Problem constants (fixed by the reference)
#define NG 128      // num_graphs
#define NT 32       // num thetas
#define NS 32       // bump steps
#define NF 128      // num features
#define NSPLIT 16   // blocks per graph
#define SCALE_F 100.0f
#define R_F 1.1f

// Scratch (device global: no allocation allowed). Layout [g][t][s]:
// sum over nodes of tanh(0.5*SCALE*(lin_s - h_{n,t})).
__device__ float g_T[NG * NT * NS];

__global__ void zero_kernel() {
    int n = NG * NT * NS;
    for (int i = blockIdx.x * blockDim.x + threadIdx.x; i < n;
         i += gridDim.x * blockDim.x)
        g_T[i] = 0.0f;
}

// batch may be int32 (JAX default) or int64 (reference dtype). n_nodes is the
// LOGICAL element count (derived from x). Probe the int32 word at n-1: for
// int64 it is the high half of element (n-1)/2 (== 0, ids < 128); for int32
// it is the last (largest, sorted) graph id != 0. In-bounds either way.
__device__ __forceinline__ bool batch_is_i64(const int* b32, int n_nodes) {
    return b32[n_nodes - 1] == 0;
}

__device__ int lower_bound_batch(const int* b32, int n, int key, bool is64) {
    const long long* b64 = (const long long*)b32;
    int lo = 0, hi = n;
    while (lo < hi) {
        int m = (lo + hi) >> 1;
        long long val = is64 ? b64[m] : (long long)b32[m];
        if (val < (long long)key) lo = m + 1; else hi = m;
    }
    return lo;
}

__device__ __forceinline__ float tanh_ap(float xv) {
    float y;
    asm("tanh.approx.f32 %0, %1;" : "=f"(y) : "f"(xv));
    return y;
}

// Packed dual-FMA: d.lo += a.lo*b.lo; d.hi += a.hi*b.hi  (one FFMA2 issue)
__device__ __forceinline__ void ffma2(unsigned long long& d,
                                      unsigned long long a,
                                      unsigned long long b) {
    asm("fma.rn.f32x2 %0, %1, %2, %0;" : "+l"(d) : "l"(a), "l"(b));
}

__global__ __launch_bounds__(256)
void ect_main_kernel(const float* __restrict__ x,
                     const int* __restrict__ batch,
                     int n_nodes,
                     const float* __restrict__ v) {
    __shared__ float vP[NF / 2][NT][2];  // 16 KB: k-pair-packed v, [k2][t][{k,k+1}]
    __shared__ float xs[32][132];        // 16.9 KB, pad 4 -> conflict-free LDS.128
    __shared__ int s_range[2];

    const int tid  = threadIdx.x;
    const int lane = tid & 31;   // doubles as: node-in-chunk (matmul) and s (window)
    const int w    = tid >> 5;   // warp id 0..7
    const int tb   = w * 4;      // this warp covers thetas tb..tb+3
    const int g    = blockIdx.x;

    const bool is64 = batch_is_i64(batch, n_nodes);

    // Pack v: v is [NT][NF] row-major -> vP[k>>1][t][k&1]
    for (int i = tid; i < NF * NT; i += 256) {
        int t = i >> 7;          // / NF
        int k = i & (NF - 1);
        vP[k >> 1][t][k & 1] = v[i];
    }
    if (tid == 0)  s_range[0] = lower_bound_batch(batch, n_nodes, g, is64);
    if (tid == 32) s_range[1] = lower_bound_batch(batch, n_nodes, g + 1, is64);
    __syncthreads();

    const int glo = s_range[0];
    const int len = s_range[1] - glo;
    const int start = glo + (int)(((long long)len * blockIdx.y) / NSPLIT);
    const int end   = glo + (int)(((long long)len * (blockIdx.y + 1)) / NSPLIT);

    const float step = (2.0f * R_F) / (NS - 1);
    // per-lane constant: 0.5*SCALE*lin_s with s = lane;  |Cs| <= 55
    const float Cs = 0.5f * SCALE_F * (-R_F + lane * step);
    // Saturation threshold: |hh| > TH  =>  |Cs - hh| > TH - 55 = 17  =>
    // tanh(Cs - hh) == -sign(hh) exactly in fp32 for every lane.
    const float TH = 72.0f;

    // Register accumulators per theta: float part (non-saturated tanh sums)
    // and integer part (saturated +/-1 counts).
    float acc0 = 0.f, acc1 = 0.f, acc2 = 0.f, acc3 = 0.f;
    int   net0 = 0,   net1 = 0,   net2 = 0,   net3 = 0;

    for (int base = start; base < end; base += 32) {
        __syncthreads();  // previous chunk's xs reads done
        // Load 32 node rows (float4, coalesced) into padded smem; pad with 0
        for (int i4 = tid; i4 < 32 * 32; i4 += 256) {
            int n  = i4 >> 5;
            int k4 = i4 & 31;
            int node = base + n;
            float4 val = make_float4(0.f, 0.f, 0.f, 0.f);
            if (node < end) val = ((const float4*)x)[(long long)node * 32 + k4];
            *(float4*)&xs[n][k4 * 4] = val;
        }
        __syncthreads();

        // Matmul: h for (node=lane, thetas tb..tb+3) via packed f32x2 FMA.
        // Per 4-k step: 8 FFMA2 + 1 LDS.128 (xs) + 4 LDS.128 (vP broadcast).
        unsigned long long p0 = 0, p1 = 0, p2 = 0, p3 = 0;
        #pragma unroll 4
        for (int k4 = 0; k4 < 32; ++k4) {
            ulonglong2 xk = *(const ulonglong2*)&xs[lane][k4 * 4];
            ulonglong2 va = *(const ulonglong2*)&vP[2 * k4][tb][0];      // t=tb,tb+1
            ulonglong2 vb = *(const ulonglong2*)&vP[2 * k4][tb + 2][0];  // t=tb+2,tb+3
            ffma2(p0, xk.x, va.x); ffma2(p1, xk.x, va.y);
            ffma2(p2, xk.x, vb.x); ffma2(p3, xk.x, vb.y);
            ulonglong2 vc = *(const ulonglong2*)&vP[2 * k4 + 1][tb][0];
            ulonglong2 vd = *(const ulonglong2*)&vP[2 * k4 + 1][tb + 2][0];
            ffma2(p0, xk.y, vc.x); ffma2(p1, xk.y, vc.y);
            ffma2(p2, xk.y, vd.x); ffma2(p3, xk.y, vd.y);
        }
        float2 f0 = *(float2*)&p0, f1 = *(float2*)&p1;
        float2 f2 = *(float2*)&p2, f3 = *(float2*)&p3;
        // hh = 0.5*SCALE*h
        float hh0 = 0.5f * SCALE_F * (f0.x + f0.y);
        float hh1 = 0.5f * SCALE_F * (f1.x + f1.y);
        float hh2 = 0.5f * SCALE_F * (f2.x + f2.y);
        float hh3 = 0.5f * SCALE_F * (f3.x + f3.y);

        // Warp transpose with saturation skip:
        //  - ballot classifies all 32 nodes per theta in 2 instructions
        //  - saturated nodes (|hh| > TH): tanh == -sign(hh) for every s lane,
        //    folded into an integer net counter (no shfl, no MUFU)
        //  - non-saturated (~34%): warp-uniform bit-scan, shfl + tanh each
        // Padded lanes (hh == 0) are excluded via vmask. Branch conditions are
        // warp-uniform (masks), so no divergence.
        const int nv = min(32, end - base);
        const unsigned vmask = (nv >= 32) ? 0xffffffffu : ((1u << nv) - 1u);
        #define ECT_PROC(hh, acc, net)                                       \
            {                                                                \
                unsigned negm = __ballot_sync(0xffffffffu, (hh) < -TH) & vmask; \
                unsigned posm = __ballot_sync(0xffffffffu, (hh) >  TH) & vmask; \
                (net) += __popc(negm) - __popc(posm);                        \
                unsigned m = vmask & ~negm & ~posm;                          \
                while (m) {                                                  \
                    int r = __ffs(m) - 1;                                    \
                    m &= m - 1;                                              \
                    float b = __shfl_sync(0xffffffffu, (hh), r);             \
                    (acc) += tanh_ap(Cs - b);                                \
                }                                                            \
            }
        ECT_PROC(hh0, acc0, net0)
        ECT_PROC(hh1, acc1, net1)
        ECT_PROC(hh2, acc2, net2)
        ECT_PROC(hh3, acc3, net3)
        #undef ECT_PROC
    }

    // Single flush per warp: coalesced global float atomics (REDG), [g][t][s]
    atomicAdd(&g_T[(g * NT + tb + 0) * NS + lane], acc0 + (float)net0);
    atomicAdd(&g_T[(g * NT + tb + 1) * NS + lane], acc1 + (float)net1);
    atomicAdd(&g_T[(g * NT + tb + 2) * NS + lane], acc2 + (float)net2);
    atomicAdd(&g_T[(g * NT + tb + 3) * NS + lane], acc3 + (float)net3);
}

// Epilogue: sigma-sum = 0.5*cnt + 0.5*T; subtract cnt * sigmoid(100*(lin_s - R))
// (the exact constant pad term). Output layout [g][s][t].
__global__ void ect_epilogue_kernel(const int* __restrict__ batch, int n_nodes,
                                    float* __restrict__ out) {
    int g = blockIdx.x;
    int t = threadIdx.x;  // 32 threads
    bool is64 = batch_is_i64(batch, n_nodes);
    __shared__ int cnt_s;
    if (t == 0) {
        int lo = lower_bound_batch(batch, n_nodes, g, is64);
        int hi = lower_bound_batch(batch, n_nodes, g + 1, is64);
        cnt_s = hi - lo;
    }
    __syncthreads();
    float cnt = (float)cnt_s;
    const float step = (2.0f * R_F) / (NS - 1);
    for (int s = 0; s < NS; s++) {
        float T = g_T[(g * NT + t) * NS + s];
        float z0 = SCALE_F * ((-R_F + s * step) - R_F);
        float s0 = 1.0f / (1.0f + expf(-z0));   // exact constant pad term
        out[(g * NS + s) * NT + t] = 0.5f * cnt + 0.5f * T - cnt * s0;
    }
}

extern "C" void kernel_launch(void* const* d_in, const int* in_sizes, int n_in,
                              void* d_out, int out_size) {
    const float* x     = (const float*)d_in[0];
    const int*   batch = (const int*)d_in[1];   // int32 or int64, sniffed on device
    const float* v     = (const float*)d_in[3];
    // Derive node count from x ([N, 128] float32) — immune to how the harness
    // counts int64 elements for the batch array.
    int n_nodes = in_sizes[0] / NF;

    zero_kernel<<<256, 256>>>();
    dim3 grid(NG, NSPLIT);
    ect_main_kernel<<<grid, 256>>>(x, batch, n_nodes, v);
    ect_epilogue_kernel<<<NG, 32>>>(batch, n_nodes, (float*)d_out);
}